// round 8
// baseline (speedup 1.0000x reference)
#include <cuda_runtime.h>
#include <stdint.h>

// MultiLevelHybridHashEncoding — instant-NGP hash-grid encoding.
// R7 -> R8: R7 was latency-limited (L1 78%, issue 43%, nothing saturated).
// Software-pipeline the GATHERS: 2 items per iteration, item B's 4 gathers
// issued while item A's are in flight -> 8 outstanding gathers/warp.
// 2 CTAs x 640 thr (40 warps/SM, 51-reg budget). Levels 0..1 stay in smem.
// Pair-coalesced gathers (lane parity = x-corner), shfl pair-reduce.

#define NLEVELS 16
#define TPB 640

#define L0_N 4096    // 16^3
#define L1_N 8000    // 20^3
#define SMEM_BYTES ((L0_N + L1_N) * 8)   // 96768 B per CTA

#define P1 2654435761u
#define P2 805459861u
#define HMASK 0x7FFFFu

struct Params {
    const float2* tab[NLEVELS];
};

__device__ __constant__ int c_res[NLEVELS] = {
    16, 20, 25, 32, 40, 50, 64, 80, 101, 128, 161, 203, 256, 322, 406, 512
};

extern __shared__ float2 s_tab[];

__global__ void __launch_bounds__(TPB, 2)
hashenc_kernel(const float* __restrict__ x, Params p,
               float2* __restrict__ out, int B)
{
    // ---- cooperative smem fill: levels 0..1, coalesced ----
    {
        const float2* __restrict__ t0 = p.tab[0];
        const float2* __restrict__ t1 = p.tab[1];
        for (int i = threadIdx.x; i < L0_N; i += TPB) s_tab[i] = __ldg(t0 + i);
        for (int i = threadIdx.x; i < L1_N; i += TPB) s_tab[L0_N + i] = __ldg(t1 + i);
    }
    __syncthreads();

    // Thread = (point, level, x-half). 32 consecutive threads = 1 point.
    const int   ox       = threadIdx.x & 1;        // x-corner this lane owns
    const int   l        = (threadIdx.x >> 1) & 15;
    const int   res      = c_res[l];
    const int   res2     = res * res;
    const float sc       = 0.5f * (float)res;
    const bool  in_smem  = (l < 2);
    const bool  use_hash = (l >= 8);
    const float2* __restrict__ gtab = p.tab[l];
    const float2* __restrict__ stab = s_tab + (l == 0 ? 0 : L0_N);

    const int total  = B * NLEVELS * 2;             // (point, level, half) items
    const int stride = gridDim.x * TPB;
    const int step   = 2 * stride;

    for (int tid = blockIdx.x * TPB + threadIdx.x; tid < total; tid += step) {
        const int tidB = tid + stride;
        const bool hasB = (tidB < total);           // warp-uniform (total % 32 == 0)
        const int bA = tid >> 5;
        const int bB = hasB ? (tidB >> 5) : bA;

        // ---- item A: compute indices/weights, ISSUE gathers ----
        float    wA[4];
        unsigned iA[4];
        {
            const float px = __ldg(x + 3 * bA + 0);
            const float py = __ldg(x + 3 * bA + 1);
            const float pz = __ldg(x + 3 * bA + 2);
            const float xp = __fadd_rn(__fmul_rn(__fadd_rn(px, 1.0f), sc), -0.5f);
            const float yp = __fadd_rn(__fmul_rn(__fadd_rn(py, 1.0f), sc), -0.5f);
            const float zp = __fadd_rn(__fmul_rn(__fadd_rn(pz, 1.0f), sc), -0.5f);
            const float fx = floorf(xp), fy = floorf(yp), fz = floorf(zp);
            const int ix = (int)fx, iy = (int)fy, iz = (int)fz;
            const float tx = __fsub_rn(xp, fx), ty = __fsub_rn(yp, fy), tz = __fsub_rn(zp, fz);
            const float ux = __fsub_rn(1.0f, tx), uy = __fsub_rn(1.0f, ty), uz = __fsub_rn(1.0f, tz);
            const int cx = ix + ox;
            const float wx = ox ? tx : ux;
            const bool vx = ((unsigned)cx < (unsigned)res);
            #pragma unroll
            for (int cc = 0; cc < 4; ++cc) {
                const int oy = (cc >> 1) & 1, oz = cc & 1;
                const int cy = iy + oy, cz = iz + oz;
                const bool valid = vx & ((unsigned)cy < (unsigned)res)
                                      & ((unsigned)cz < (unsigned)res);
                const float ww = __fmul_rn(__fmul_rn(wx, oy ? ty : uy), oz ? tz : uz);
                wA[cc] = valid ? ww : 0.0f;
                const unsigned h = ((unsigned)cx ^ ((unsigned)cy * P1)
                                                 ^ ((unsigned)cz * P2)) & HMASK;
                const unsigned d = (unsigned)(cx + cy * res + cz * res2);
                iA[cc] = valid ? (use_hash ? h : d) : 0u;
            }
        }
        float2 eA[4];
        if (in_smem) {
            #pragma unroll
            for (int cc = 0; cc < 4; ++cc) eA[cc] = stab[iA[cc]];
        } else {
            #pragma unroll
            for (int cc = 0; cc < 4; ++cc) eA[cc] = __ldg(&gtab[iA[cc]]);
        }

        // ---- item B: compute indices/weights, ISSUE gathers (A in flight) ----
        float    wB[4];
        unsigned iB[4];
        {
            const float px = __ldg(x + 3 * bB + 0);
            const float py = __ldg(x + 3 * bB + 1);
            const float pz = __ldg(x + 3 * bB + 2);
            const float xp = __fadd_rn(__fmul_rn(__fadd_rn(px, 1.0f), sc), -0.5f);
            const float yp = __fadd_rn(__fmul_rn(__fadd_rn(py, 1.0f), sc), -0.5f);
            const float zp = __fadd_rn(__fmul_rn(__fadd_rn(pz, 1.0f), sc), -0.5f);
            const float fx = floorf(xp), fy = floorf(yp), fz = floorf(zp);
            const int ix = (int)fx, iy = (int)fy, iz = (int)fz;
            const float tx = __fsub_rn(xp, fx), ty = __fsub_rn(yp, fy), tz = __fsub_rn(zp, fz);
            const float ux = __fsub_rn(1.0f, tx), uy = __fsub_rn(1.0f, ty), uz = __fsub_rn(1.0f, tz);
            const int cx = ix + ox;
            const float wx = ox ? tx : ux;
            const bool vx = ((unsigned)cx < (unsigned)res);
            #pragma unroll
            for (int cc = 0; cc < 4; ++cc) {
                const int oy = (cc >> 1) & 1, oz = cc & 1;
                const int cy = iy + oy, cz = iz + oz;
                const bool valid = vx & ((unsigned)cy < (unsigned)res)
                                      & ((unsigned)cz < (unsigned)res);
                const float ww = __fmul_rn(__fmul_rn(wx, oy ? ty : uy), oz ? tz : uz);
                wB[cc] = valid ? ww : 0.0f;
                const unsigned h = ((unsigned)cx ^ ((unsigned)cy * P1)
                                                 ^ ((unsigned)cz * P2)) & HMASK;
                const unsigned d = (unsigned)(cx + cy * res + cz * res2);
                iB[cc] = valid ? (use_hash ? h : d) : 0u;
            }
        }
        float2 eB[4];
        if (in_smem) {
            #pragma unroll
            for (int cc = 0; cc < 4; ++cc) eB[cc] = stab[iB[cc]];
        } else {
            #pragma unroll
            for (int cc = 0; cc < 4; ++cc) eB[cc] = __ldg(&gtab[iB[cc]]);
        }

        // ---- consume A ----
        {
            float a0 = 0.0f, a1 = 0.0f;
            #pragma unroll
            for (int cc = 0; cc < 4; ++cc) {
                a0 = fmaf(eA[cc].x, wA[cc], a0);
                a1 = fmaf(eA[cc].y, wA[cc], a1);
            }
            a0 += __shfl_xor_sync(0xffffffffu, a0, 1);
            a1 += __shfl_xor_sync(0xffffffffu, a1, 1);
            if (ox == 0) {
                __stcs(&out[(size_t)bA * NLEVELS + l], make_float2(a0, a1));
            }
        }

        // ---- consume B ----
        if (hasB) {
            float a0 = 0.0f, a1 = 0.0f;
            #pragma unroll
            for (int cc = 0; cc < 4; ++cc) {
                a0 = fmaf(eB[cc].x, wB[cc], a0);
                a1 = fmaf(eB[cc].y, wB[cc], a1);
            }
            a0 += __shfl_xor_sync(0xffffffffu, a0, 1);
            a1 += __shfl_xor_sync(0xffffffffu, a1, 1);
            if (ox == 0) {
                __stcs(&out[(size_t)bB * NLEVELS + l], make_float2(a0, a1));
            }
        }
    }
}

extern "C" void kernel_launch(void* const* d_in, const int* in_sizes, int n_in,
                              void* d_out, int out_size)
{
    const float* x = (const float*)d_in[0];
    Params p;
    #pragma unroll
    for (int l = 0; l < NLEVELS; ++l) {
        p.tab[l] = (const float2*)d_in[1 + l];
    }
    const int B = in_sizes[0] / 3;

    cudaFuncSetAttribute(hashenc_kernel,
                         cudaFuncAttributeMaxDynamicSharedMemorySize, SMEM_BYTES);

    int sms = 148;
    cudaDeviceGetAttribute(&sms, cudaDevAttrMultiProcessorCount, 0);

    hashenc_kernel<<<2 * sms, TPB, SMEM_BYTES>>>(x, p, (float2*)d_out, B);
}